// round 9
// baseline (speedup 1.0000x reference)
#include <cuda_runtime.h>
#include <cuda_bf16.h>
#include <cstdint>
#include <cstdio>

#define TLTOT 40000
#define NTOP  1000
#define KCDIM 256
#define BM    64
#define BN    64
#define PITCH 264     // bf16 per A/B SMEM row (256+8 pad, LDSM conflict-free)
#define RCPITCH 68    // floats per staged R/C row (16B-aligned rows, conflict-free LDS)
#define NT_TILES 16   // ceil(1000/64)

// SMEM: Ah,Al,Bh,Bl (4 x 64*264*2 = 135168) + sR,sC dbl (2 x 2 x 64*68*4 = 69632)
#define A_BYTES   (BM*PITCH*2)
#define B_BYTES   (BN*PITCH*2)
#define RC_BYTES  (BM*RCPITCH*4)
#define OFF_AH    0
#define OFF_AL    (OFF_AH + A_BYTES)
#define OFF_BH    (OFF_AL + A_BYTES)
#define OFF_BL    (OFF_BH + B_BYTES)
#define OFF_R     (OFF_BL + B_BYTES)
#define OFF_C     (OFF_R + 2*RC_BYTES)
#define SMEM_BYTES (OFF_C + 2*RC_BYTES)   // 204800

#define LOGC 1.3836465597893728f   // -log(0.1) - 0.5*log(2*pi)

__device__ __nv_bfloat16 g_Bhi[NTOP * KCDIM];
__device__ __nv_bfloat16 g_Blo[NTOP * KCDIM];

// ---------------------------------------------------------------------------
// Kernel 1 (coalesced): column-sums of nw, build split-bf16 V_j, zero d_out
// ---------------------------------------------------------------------------
__global__ void setup_kernel(const float* __restrict__ V,
                             const float* __restrict__ nw,
                             const float* __restrict__ noise,
                             float* __restrict__ out)
{
    __shared__ float s_part[8][32];
    __shared__ float s_sum[32];
    const int t   = threadIdx.x;
    const int b   = blockIdx.x;
    const int cl  = t & 31;
    const int rg  = t >> 5;
    const int col = b * 32 + cl;

    float s = 0.f;
    if (col < NTOP) {
        for (int i = rg; i < NTOP; i += 8)
            s += nw[i * NTOP + col];
    }
    s_part[rg][cl] = s;
    __syncthreads();
    if (rg == 0) {
        float v = s_part[0][cl];
        #pragma unroll
        for (int g = 1; g < 8; g++) v += s_part[g][cl];
        s_sum[cl] = v;
    }
    __syncthreads();

    for (int idx = t; idx < 32 * KCDIM; idx += 256) {
        int jl = idx >> 8;
        int k  = idx & 255;
        int jg = b * 32 + jl;
        if (jg < NTOP) {
            int g = jg * KCDIM + k;
            float v = fmaf(V[g], s_sum[jl], 0.1f * noise[g]);
            __nv_bfloat16 h = __float2bfloat16(v);
            g_Bhi[g] = h;
            g_Blo[g] = __float2bfloat16(v - __bfloat162float(h));
        }
    }
    if (b == 0 && t == 0) *out = 0.f;
}

// ---------------------------------------------------------------------------
// helpers
// ---------------------------------------------------------------------------
__device__ __forceinline__ void ldsm4(uint32_t* r, uint32_t saddr) {
    asm volatile("ldmatrix.sync.aligned.m8n8.x4.shared.b16 {%0,%1,%2,%3}, [%4];\n"
                 : "=r"(r[0]), "=r"(r[1]), "=r"(r[2]), "=r"(r[3]) : "r"(saddr));
}
__device__ __forceinline__ void ldsm2(uint32_t* r, uint32_t saddr) {
    asm volatile("ldmatrix.sync.aligned.m8n8.x2.shared.b16 {%0,%1}, [%2];\n"
                 : "=r"(r[0]), "=r"(r[1]) : "r"(saddr));
}
__device__ __forceinline__ void mma16816(float* c, const uint32_t* a, uint32_t b0, uint32_t b1) {
    asm volatile(
        "mma.sync.aligned.m16n8k16.row.col.f32.bf16.bf16.f32 "
        "{%0,%1,%2,%3},{%4,%5,%6,%7},{%8,%9},{%0,%1,%2,%3};\n"
        : "+f"(c[0]), "+f"(c[1]), "+f"(c[2]), "+f"(c[3])
        : "r"(a[0]), "r"(a[1]), "r"(a[2]), "r"(a[3]), "r"(b0), "r"(b1));
}
__device__ __forceinline__ void cpasync16(uint32_t saddr, const void* g) {
    asm volatile("cp.async.cg.shared.global [%0], [%1], 16;\n" :: "r"(saddr), "l"(g));
}
__device__ __forceinline__ float sigmoidf(float x) {
    return __fdividef(1.f, 1.f + __expf(-x));
}
__device__ __forceinline__ uint32_t packbf2(float a, float b) {
    __nv_bfloat162 p = __floats2bfloat162_rn(a, b);
    return *(uint32_t*)&p;
}

// ---------------------------------------------------------------------------
// Kernel 2: fused U_emb + split-bf16 GEMM + sigmoid + masked logprob
// 1024 threads: 4 warps over M (16 rows) x 8 warps over N (8 cols).
// R/C streamed via cp.async into double-buffered SMEM one tile ahead.
// ---------------------------------------------------------------------------
__global__ void __launch_bounds__(1024, 1)
main_kernel(const float* __restrict__ R,
            const float* __restrict__ U,
            const float* __restrict__ W,
            const float* __restrict__ Bb,
            const int*   __restrict__ C,
            float* __restrict__ out)
{
    extern __shared__ __align__(16) char smem[];
    __nv_bfloat16* Ah = (__nv_bfloat16*)(smem + OFF_AH);
    __nv_bfloat16* Al = (__nv_bfloat16*)(smem + OFF_AL);
    __nv_bfloat16* Bh = (__nv_bfloat16*)(smem + OFF_BH);
    __nv_bfloat16* Bl = (__nv_bfloat16*)(smem + OFF_BL);
    const float*   sR = (const float*)(smem + OFF_R);
    const int*     sC = (const int*)(smem + OFF_C);
    __shared__ float red[32];

    const int tid  = threadIdx.x;
    const int lane = tid & 31;
    const int warp = tid >> 5;
    const int wm   = warp & 3;    // 4 warps over M (16 rows)
    const int wn   = warp >> 2;   // 8 warps over N (8 cols)
    const int rowbase = blockIdx.x * BM;   // 625*64 = 40000 exactly, no row guard

    const uint32_t sbase = (uint32_t)__cvta_generic_to_shared(smem);

    // cp.async coords: thread -> (row, 16B chunk)
    const int rcrow = tid >> 4;       // 0..63
    const int rcc4  = tid & 15;       // 0..15 (cols rcc4*4..+3)

    // ---- pre-issue R/C tile 0 ----
    {
        if (rcc4 * 4 < NTOP) {
            size_t goff = (size_t)(rowbase + rcrow) * NTOP + rcc4 * 4;
            uint32_t so = (uint32_t)(rcrow * RCPITCH + rcc4 * 4) * 4;
            cpasync16(sbase + OFF_R + so, R + goff);
            cpasync16(sbase + OFF_C + so, C + goff);
        }
        asm volatile("cp.async.commit_group;\n" ::: "memory");
    }

    // ---- Phase 1: U_emb (fp32) -> split bf16 A tile; float4 U loads ----
    {
        const float w0 = W[0], w1 = W[1], w2 = W[2], w3 = W[3], w4 = W[4];
        const float bb = Bb[0];
        #pragma unroll
        for (int i = 0; i < (BM * (KCDIM / 4)) / 1024; i++) {   // 4 iters
            int idx = tid + i * 1024;
            int r  = idx >> 6;          // 0..63
            int kg = idx & 63;          // k-group of 4
            int k0 = kg * 4;
            const float4* up = (const float4*)(U + ((size_t)(rowbase + r) * (KCDIM * 5) + (size_t)k0 * 5));
            float4 f0 = __ldcs(up + 0);
            float4 f1 = __ldcs(up + 1);
            float4 f2 = __ldcs(up + 2);
            float4 f3 = __ldcs(up + 3);
            float4 f4 = __ldcs(up + 4);
            const float f[20] = {f0.x,f0.y,f0.z,f0.w, f1.x,f1.y,f1.z,f1.w,
                                 f2.x,f2.y,f2.z,f2.w, f3.x,f3.y,f3.z,f3.w,
                                 f4.x,f4.y,f4.z,f4.w};
            float o[4], ol[4];
            #pragma unroll
            for (int q = 0; q < 4; q++) {
                float v = bb;
                v = fmaf(f[q*5+0], w0, v);
                v = fmaf(f[q*5+1], w1, v);
                v = fmaf(f[q*5+2], w2, v);
                v = fmaf(f[q*5+3], w3, v);
                v = fmaf(f[q*5+4], w4, v);
                float h = __bfloat162float(__float2bfloat16(v));
                o[q]  = v;          // hi rounds inside pack
                ol[q] = v - h;
            }
            *(uint2*)(Ah + r * PITCH + k0) = make_uint2(packbf2(o[0], o[1]),  packbf2(o[2], o[3]));
            *(uint2*)(Al + r * PITCH + k0) = make_uint2(packbf2(ol[0], ol[1]), packbf2(ol[2], ol[3]));
        }
    }

    // ldmatrix lane addresses (bytes)
    const uint32_t arow = (uint32_t)((wm * 16 + (lane & 15)) * PITCH + (lane >> 4) * 8) * 2;
    const uint32_t boff = (uint32_t)((wn * 8 + (lane & 7)) * PITCH + ((lane >> 3) & 1) * 8) * 2;
    const uint32_t sAh = sbase + OFF_AH, sAl = sbase + OFF_AL;
    const uint32_t sBh = sbase + OFF_BH, sBl = sbase + OFF_BL;

    // epilogue coords (SMEM-local)
    const int er  = wm * 16 + (lane >> 2);       // rows er, er+8
    const int ejc = wn * 8 + ((lane & 3) << 1);  // cols ejc, ejc+1

    float lsum = 0.f;

    for (int t = 0; t < NT_TILES; t++) {
        const int j0 = t * BN;
        __syncthreads();   // prev MMA done with B; prev epilogue done with rcbuf[t&1]

        // ---- issue R/C for tile t+1 ----
        if (t + 1 < NT_TILES) {
            const int j1 = j0 + BN;
            if (rcc4 * 4 < NTOP - j1) {
                size_t goff = (size_t)(rowbase + rcrow) * NTOP + j1 + rcc4 * 4;
                uint32_t so = (uint32_t)(((t + 1) & 1) * BM * RCPITCH + rcrow * RCPITCH + rcc4 * 4) * 4;
                cpasync16(sbase + OFF_R + so, R + goff);
                cpasync16(sbase + OFF_C + so, C + goff);
            }
            asm volatile("cp.async.commit_group;\n" ::: "memory");
        }

        // ---- stage B tile t (L2-resident) ----
        #pragma unroll
        for (int v = 0; v < 2; v++) {
            int idx = tid + v * 1024;          // 2048 chunks
            int n  = idx >> 5;
            int c8 = idx & 31;
            int jj = j0 + n;
            uint4 hv = make_uint4(0, 0, 0, 0), lv = make_uint4(0, 0, 0, 0);
            if (jj < NTOP) {
                hv = *(const uint4*)(g_Bhi + jj * KCDIM + c8 * 8);
                lv = *(const uint4*)(g_Blo + jj * KCDIM + c8 * 8);
            }
            *(uint4*)(Bh + n * PITCH + c8 * 8) = hv;
            *(uint4*)(Bl + n * PITCH + c8 * 8) = lv;
        }

        // ---- wait for R/C tile t (t+1 may stay in flight) ----
        if (t + 1 < NT_TILES)
            asm volatile("cp.async.wait_group 1;\n" ::: "memory");
        else
            asm volatile("cp.async.wait_group 0;\n" ::: "memory");
        __syncthreads();

        // ---- MMA: acc = Ah*Bh + Al*Bh + Ah*Bl ----
        float acc[4] = {};
        #pragma unroll 4
        for (int ks = 0; ks < 16; ks++) {
            const uint32_t k0b = (uint32_t)(ks * 16) * 2;
            uint32_t ah[4], al[4], bh[2], bl[2];
            ldsm4(ah, sAh + arow + k0b);
            ldsm4(al, sAl + arow + k0b);
            ldsm2(bh, sBh + boff + k0b);
            ldsm2(bl, sBl + boff + k0b);
            mma16816(acc, ah, bh[0], bh[1]);
            mma16816(acc, al, bh[0], bh[1]);
            mma16816(acc, ah, bl[0], bl[1]);
        }

        // ---- epilogue: R/C from staged SMEM ----
        if (j0 + ejc < NTOP) {
            const int bufo = (t & 1) * BM * RCPITCH;
            #pragma unroll
            for (int rr = 0; rr < 2; rr++) {
                const int so = bufo + (er + rr * 8) * RCPITCH + ejc;
                float2 r2 = *(const float2*)(sR + so);
                int2   c2 = *(const int2*)(sC + so);
                if (c2.x == 1) { float m = sigmoidf(acc[rr*2+0]); float z = (r2.x - m) * 10.f; lsum += LOGC - 0.5f * z * z; }
                if (c2.y == 1) { float m = sigmoidf(acc[rr*2+1]); float z = (r2.y - m) * 10.f; lsum += LOGC - 0.5f * z * z; }
            }
        }
    }

    // ---- reduction ----
    #pragma unroll
    for (int o = 16; o > 0; o >>= 1)
        lsum += __shfl_xor_sync(0xFFFFFFFFu, lsum, o);
    if (lane == 0) red[warp] = lsum;
    __syncthreads();
    if (warp == 0) {
        float v = red[lane];
        #pragma unroll
        for (int o = 16; o > 0; o >>= 1)
            v += __shfl_xor_sync(0xFFFFFFFFu, v, o);
        if (lane == 0) atomicAdd(out, v);
    }
}

// ---------------------------------------------------------------------------
extern "C" void kernel_launch(void* const* d_in, const int* in_sizes, int n_in,
                              void* d_out, int out_size)
{
    // Identify inputs by element count (dict order breaks ties:
    // V before noise at 256000, R before C at 40000000).
    const float *V = nullptr, *R = nullptr, *nw = nullptr, *U = nullptr;
    const float *W = nullptr, *Bb = nullptr, *noise = nullptr;
    const int* C = nullptr;
    int seen256k = 0, seen40m = 0;
    for (int i = 0; i < n_in; i++) {
        switch (in_sizes[i]) {
            case 256000:
                if (seen256k++ == 0) V = (const float*)d_in[i];
                else                 noise = (const float*)d_in[i];
                break;
            case 40000000:
                if (seen40m++ == 0) R = (const float*)d_in[i];
                else                C = (const int*)d_in[i];
                break;
            case 1000000:  nw = (const float*)d_in[i]; break;
            case 51200000: U  = (const float*)d_in[i]; break;
            case 5:        W  = (const float*)d_in[i]; break;
            case 1:        Bb = (const float*)d_in[i]; break;
            default: break; // Q unused
        }
    }
    float* out = (float*)d_out;

    cudaFuncSetAttribute(main_kernel, cudaFuncAttributeMaxDynamicSharedMemorySize, SMEM_BYTES);

    setup_kernel<<<32, 256>>>(V, nw, noise, out);
    main_kernel<<<TLTOT / BM, 1024, SMEM_BYTES>>>(R, U, W, Bb, C, out);
}

// round 11
// speedup vs baseline: 1.3345x; 1.3345x over previous
#include <cuda_runtime.h>
#include <cuda_bf16.h>
#include <cstdint>

#define TLTOT 40000
#define NTOP  1000
#define NTPAD 1024          // g_B rows padded: tail tile reads zeros, no guards
#define KCDIM 256
#define BM    64
#define BN    64
#define NT    16            // 1024/64 j-tiles (tail zero-padded)
#define PITCH 264           // bf16 per SMEM row (256+8 pad, LDSM conflict-free)
#define NTHREADS 640        // 16 consumer warps + 4 producer warps
#define NCTHREADS 512

#define A_MAT   (BM*PITCH*2)        // 33792
#define B_MAT   (BN*PITCH*2)        // 33792
#define B_STAGE (2*B_MAT)           // hi+lo
#define OFF_AH  0
#define OFF_AL  A_MAT
#define OFF_B   (2*A_MAT)           // [stage][hi/lo]
#define OFF_MB  (OFF_B + 2*B_STAGE) // 202752 ; full0,full1,empty0,empty1
#define SMEM_BYTES (OFF_MB + 32)

#define LOGC 1.3836465597893728f    // -log(0.1) - 0.5*log(2*pi)

__device__ __nv_bfloat16 g_Bhi[NTPAD * KCDIM];
__device__ __nv_bfloat16 g_Blo[NTPAD * KCDIM];

// ---------------------------------------------------------------------------
// Kernel 1: column-sums of nw, split-bf16 V_j (rows >= NTOP zero-filled)
// ---------------------------------------------------------------------------
__global__ void setup_kernel(const float* __restrict__ V,
                             const float* __restrict__ nw,
                             const float* __restrict__ noise,
                             float* __restrict__ out)
{
    __shared__ float s_part[8][32];
    __shared__ float s_sum[32];
    const int t   = threadIdx.x;
    const int b   = blockIdx.x;
    const int cl  = t & 31;
    const int rg  = t >> 5;
    const int col = b * 32 + cl;

    float s = 0.f;
    if (col < NTOP) {
        for (int i = rg; i < NTOP; i += 8)
            s += nw[i * NTOP + col];
    }
    s_part[rg][cl] = s;
    __syncthreads();
    if (rg == 0) {
        float v = s_part[0][cl];
        #pragma unroll
        for (int g = 1; g < 8; g++) v += s_part[g][cl];
        s_sum[cl] = v;
    }
    __syncthreads();

    for (int idx = t; idx < 32 * KCDIM; idx += 256) {
        int jl = idx >> 8;
        int k  = idx & 255;
        int jg = b * 32 + jl;                 // < 1024 (32 blocks)
        int g  = jg * KCDIM + k;
        float v = 0.f;
        if (jg < NTOP) v = fmaf(V[g], s_sum[jl], 0.1f * noise[g]);
        __nv_bfloat16 h = __float2bfloat16(v);
        g_Bhi[g] = h;
        g_Blo[g] = __float2bfloat16(v - __bfloat162float(h));
    }
    if (b == 0 && t == 0) *out = 0.f;
}

// ---------------------------------------------------------------------------
// helpers (base ISA only: ldmatrix / mma.sync / cp.async / mbarrier)
// ---------------------------------------------------------------------------
__device__ __forceinline__ void ldsm4(uint32_t* r, uint32_t saddr) {
    asm volatile("ldmatrix.sync.aligned.m8n8.x4.shared.b16 {%0,%1,%2,%3}, [%4];\n"
                 : "=r"(r[0]), "=r"(r[1]), "=r"(r[2]), "=r"(r[3]) : "r"(saddr));
}
__device__ __forceinline__ void mma16816(float* c, const uint32_t* a, uint32_t b0, uint32_t b1) {
    asm volatile(
        "mma.sync.aligned.m16n8k16.row.col.f32.bf16.bf16.f32 "
        "{%0,%1,%2,%3},{%4,%5,%6,%7},{%8,%9},{%0,%1,%2,%3};\n"
        : "+f"(c[0]), "+f"(c[1]), "+f"(c[2]), "+f"(c[3])
        : "r"(a[0]), "r"(a[1]), "r"(a[2]), "r"(a[3]), "r"(b0), "r"(b1));
}
__device__ __forceinline__ void cpasync16(uint32_t saddr, const void* g) {
    asm volatile("cp.async.cg.shared.global [%0], [%1], 16;\n" :: "r"(saddr), "l"(g));
}
__device__ __forceinline__ void mbar_wait(uint32_t mbar, uint32_t parity) {
    asm volatile(
        "{\n\t.reg .pred P;\n\t"
        "WL_%=:\n\t"
        "mbarrier.try_wait.parity.acquire.cta.shared::cta.b64 P, [%0], %1, 0x989680;\n\t"
        "@P bra WD_%=;\n\t"
        "bra WL_%=;\n\t"
        "WD_%=:\n\t}"
        :: "r"(mbar), "r"(parity) : "memory");
}
__device__ __forceinline__ void mbar_arrive(uint32_t mbar) {
    asm volatile("mbarrier.arrive.shared.b64 _, [%0];" :: "r"(mbar) : "memory");
}
__device__ __forceinline__ float sigmoidf(float x) {
    return __fdividef(1.f, 1.f + __expf(-x));
}
__device__ __forceinline__ uint32_t packbf2(float a, float b) {
    __nv_bfloat162 p = __floats2bfloat162_rn(a, b);
    return *(uint32_t*)&p;
}

// ---------------------------------------------------------------------------
// Kernel 2: warp-specialized fused kernel.
// Consumers (warps 0-15): A fill, LDSM+MMA (bf16x3 split), epilogue.
// Producers (warps 16-19): cp.async B tiles into 2-stage ring w/ mbarriers.
// ---------------------------------------------------------------------------
__global__ void __launch_bounds__(NTHREADS, 1)
main_kernel(const float* __restrict__ R,
            const float* __restrict__ U,
            const float* __restrict__ W,
            const float* __restrict__ Bb,
            const int*   __restrict__ C,
            float* __restrict__ out)
{
    extern __shared__ __align__(16) char smem[];
    __shared__ float red[20];
    const uint32_t sb = (uint32_t)__cvta_generic_to_shared(smem);
    const uint32_t mb_full  = sb + OFF_MB;        // +0, +8
    const uint32_t mb_empty = sb + OFF_MB + 16;   // +0, +8

    const int tid  = threadIdx.x;
    const int lane = tid & 31;
    const int warp = tid >> 5;
    const int rowbase = blockIdx.x * BM;          // 625*64 = 40000 exact

    if (tid == 0) {
        asm volatile("mbarrier.init.shared.b64 [%0], %1;" :: "r"(mb_full),      "r"(128u) : "memory");
        asm volatile("mbarrier.init.shared.b64 [%0], %1;" :: "r"(mb_full + 8),  "r"(128u) : "memory");
        asm volatile("mbarrier.init.shared.b64 [%0], %1;" :: "r"(mb_empty),     "r"(512u) : "memory");
        asm volatile("mbarrier.init.shared.b64 [%0], %1;" :: "r"(mb_empty + 8), "r"(512u) : "memory");
    }
    __syncthreads();   // mbars initialized for everyone

    float lsum = 0.f;

    if (warp >= 16) {
        // ================= PRODUCER (4 warps, 128 threads) =================
        const int ptid = tid - NCTHREADS;
        for (int t = 0; t < NT; t++) {
            const int s = t & 1;
            const uint32_t pp = (((uint32_t)t >> 1) & 1u) ^ 1u;   // first waits pass
            mbar_wait(mb_empty + s * 8, pp);
            const int j0 = t * BN;
            const uint32_t dbase = sb + OFF_B + (uint32_t)s * B_STAGE;
            #pragma unroll
            for (int i = 0; i < 32; i++) {
                int c   = i * 128 + ptid;       // 0..4095
                int mat = c >> 11;              // 0=hi 1=lo
                int rem = c & 2047;
                int n   = rem >> 5;             // 0..63
                int c8  = rem & 31;             // k-chunk of 8
                const __nv_bfloat16* src =
                    (mat ? g_Blo : g_Bhi) + (size_t)(j0 + n) * KCDIM + c8 * 8;
                cpasync16(dbase + (uint32_t)mat * B_MAT +
                          (uint32_t)(n * PITCH + c8 * 8) * 2, src);
            }
            asm volatile("cp.async.commit_group;\n" ::: "memory");
            asm volatile("cp.async.wait_group 0;\n" ::: "memory");
            mbar_arrive(mb_full + s * 8);
        }
    } else {
        // ================= CONSUMER (16 warps, 512 threads) =================
        const int wm = warp & 3;     // 4 over M (16 rows)
        const int wn = warp >> 2;    // 4 over N (16 cols)

        // ---- A fill: U_emb -> split bf16 (hi/lo) ----
        {
            const float w0 = W[0], w1 = W[1], w2 = W[2], w3 = W[3], w4 = W[4];
            const float bb = Bb[0];
            __nv_bfloat16* Ah = (__nv_bfloat16*)(smem + OFF_AH);
            __nv_bfloat16* Al = (__nv_bfloat16*)(smem + OFF_AL);
            #pragma unroll
            for (int i = 0; i < (BM * (KCDIM / 4)) / NCTHREADS; i++) {   // 8 iters
                int idx = tid + i * NCTHREADS;
                int r  = idx >> 6;          // 0..63
                int k0 = (idx & 63) * 4;
                const float4* up = (const float4*)(U + ((size_t)(rowbase + r) * (KCDIM * 5) + (size_t)k0 * 5));
                float4 f0 = __ldcs(up + 0);
                float4 f1 = __ldcs(up + 1);
                float4 f2 = __ldcs(up + 2);
                float4 f3 = __ldcs(up + 3);
                float4 f4 = __ldcs(up + 4);
                const float f[20] = {f0.x,f0.y,f0.z,f0.w, f1.x,f1.y,f1.z,f1.w,
                                     f2.x,f2.y,f2.z,f2.w, f3.x,f3.y,f3.z,f3.w,
                                     f4.x,f4.y,f4.z,f4.w};
                float o[4], ol[4];
                #pragma unroll
                for (int q = 0; q < 4; q++) {
                    float v = bb;
                    v = fmaf(f[q*5+0], w0, v);
                    v = fmaf(f[q*5+1], w1, v);
                    v = fmaf(f[q*5+2], w2, v);
                    v = fmaf(f[q*5+3], w3, v);
                    v = fmaf(f[q*5+4], w4, v);
                    o[q]  = v;
                    ol[q] = v - __bfloat162float(__float2bfloat16(v));
                }
                *(uint2*)(Ah + r * PITCH + k0) = make_uint2(packbf2(o[0], o[1]),  packbf2(o[2], o[3]));
                *(uint2*)(Al + r * PITCH + k0) = make_uint2(packbf2(ol[0], ol[1]), packbf2(ol[2], ol[3]));
            }
        }
        asm volatile("bar.sync 1, %0;" :: "n"(NCTHREADS) : "memory");   // consumers only

        // ldmatrix lane addresses (bytes)
        const uint32_t arow = (uint32_t)((wm * 16 + (lane & 15)) * PITCH + (lane >> 4) * 8) * 2;
        const uint32_t boff = (uint32_t)((wn * 16 + ((lane >> 4) & 1) * 8 + (lane & 7)) * PITCH
                               + ((lane >> 3) & 1) * 8) * 2;
        const uint32_t sAh = sb + OFF_AH, sAl = sb + OFF_AL;

        // epilogue coords
        const int er0 = rowbase + wm * 16 + (lane >> 2);   // rows er0, er0+8
        const int ejc = wn * 16 + ((lane & 3) << 1);       // + j0 + ni*8

        for (int t = 0; t < NT; t++) {
            const int s = t & 1;
            const uint32_t pc = ((uint32_t)t >> 1) & 1u;
            const int j0 = t * BN;

            // ---- prefetch R/C (DRAM latency overlaps full-wait + MMA) ----
            float2 rv[2][2];
            int2   cvv[2][2];
            #pragma unroll
            for (int ni = 0; ni < 2; ni++) {
                #pragma unroll
                for (int rr = 0; rr < 2; rr++) {
                    cvv[ni][rr] = make_int2(0, 0);
                    const int jc = j0 + ejc + ni * 8;
                    if (jc < NTOP) {
                        const size_t off = (size_t)(er0 + rr * 8) * NTOP + jc;
                        rv[ni][rr]  = __ldcs((const float2*)(R + off));
                        cvv[ni][rr] = __ldcs((const int2*)(C + off));
                    }
                }
            }

            mbar_wait(mb_full + s * 8, pc);

            // ---- MMA: acc = Ah*Bh + Al*Bh + Ah*Bl ----
            const uint32_t sBh = sb + OFF_B + (uint32_t)s * B_STAGE;
            const uint32_t sBl = sBh + B_MAT;
            float acc[2][4] = {};
            #pragma unroll 4
            for (int ks = 0; ks < 16; ks++) {
                const uint32_t k0b = (uint32_t)(ks * 16) * 2;
                uint32_t ah[4], al[4], bh[4], bl[4];
                ldsm4(ah, sAh + arow + k0b);
                ldsm4(al, sAl + arow + k0b);
                ldsm4(bh, sBh + boff + k0b);
                ldsm4(bl, sBl + boff + k0b);
                #pragma unroll
                for (int ni = 0; ni < 2; ni++) {
                    const int s2 = ni * 2;
                    mma16816(acc[ni], ah, bh[s2], bh[s2 + 1]);
                    mma16816(acc[ni], al, bh[s2], bh[s2 + 1]);
                    mma16816(acc[ni], ah, bl[s2], bl[s2 + 1]);
                }
            }
            mbar_arrive(mb_empty + s * 8);   // free stage before epilogue math

            // ---- epilogue ----
            #pragma unroll
            for (int ni = 0; ni < 2; ni++) {
                #pragma unroll
                for (int rr = 0; rr < 2; rr++) {
                    const float2 r2 = rv[ni][rr];
                    const int2   c2 = cvv[ni][rr];
                    if (c2.x == 1) { float m = sigmoidf(acc[ni][rr*2+0]); float z = (r2.x - m) * 10.f; lsum += LOGC - 0.5f * z * z; }
                    if (c2.y == 1) { float m = sigmoidf(acc[ni][rr*2+1]); float z = (r2.y - m) * 10.f; lsum += LOGC - 0.5f * z * z; }
                }
            }
        }
    }

    // ---- block reduction (all 640 threads; producers contribute 0) ----
    #pragma unroll
    for (int o = 16; o > 0; o >>= 1)
        lsum += __shfl_xor_sync(0xFFFFFFFFu, lsum, o);
    if (lane == 0) red[warp] = lsum;
    __syncthreads();
    if (warp == 0) {
        float v = (lane < 20) ? red[lane] : 0.f;
        #pragma unroll
        for (int o = 16; o > 0; o >>= 1)
            v += __shfl_xor_sync(0xFFFFFFFFu, v, o);
        if (lane == 0) atomicAdd(out, v);
    }
}

// ---------------------------------------------------------------------------
extern "C" void kernel_launch(void* const* d_in, const int* in_sizes, int n_in,
                              void* d_out, int out_size)
{
    // Identify inputs by element count (dict order breaks ties:
    // V before noise at 256000, R before C at 40000000).
    const float *V = nullptr, *R = nullptr, *nw = nullptr, *U = nullptr;
    const float *W = nullptr, *Bb = nullptr, *noise = nullptr;
    const int* C = nullptr;
    int seen256k = 0, seen40m = 0;
    for (int i = 0; i < n_in; i++) {
        switch (in_sizes[i]) {
            case 256000:
                if (seen256k++ == 0) V = (const float*)d_in[i];
                else                 noise = (const float*)d_in[i];
                break;
            case 40000000:
                if (seen40m++ == 0) R = (const float*)d_in[i];
                else                C = (const int*)d_in[i];
                break;
            case 1000000:  nw = (const float*)d_in[i]; break;
            case 51200000: U  = (const float*)d_in[i]; break;
            case 5:        W  = (const float*)d_in[i]; break;
            case 1:        Bb = (const float*)d_in[i]; break;
            default: break; // Q unused
        }
    }
    float* out = (float*)d_out;

    cudaFuncSetAttribute(main_kernel, cudaFuncAttributeMaxDynamicSharedMemorySize, SMEM_BYTES);

    setup_kernel<<<32, 256>>>(V, nw, noise, out);
    main_kernel<<<TLTOT / BM, NTHREADS, SMEM_BYTES>>>(R, U, W, Bb, C, out);
}

// round 12
// speedup vs baseline: 1.3499x; 1.0115x over previous
#include <cuda_runtime.h>
#include <cuda_fp16.h>
#include <cuda_bf16.h>
#include <cstdint>

#define TLTOT 40000
#define NTOP  1000
#define NTPAD 1024          // g_B rows padded: tail tile reads zeros, no guards
#define KCDIM 256
#define BM    128
#define BN    64
#define NT    16            // 1024/64 j-tiles (tail zero-padded)
#define PITCH 264           // fp16 per SMEM row (256+8 pad, LDSM conflict-free)
#define NTHREADS 640        // 16 consumer warps + 4 producer warps
#define NCTHREADS 512

#define A_MAT   (BM*PITCH*2)        // 67584 (one of Ah/Al)
#define B_MAT   (BN*PITCH*2)        // 33792 (single fp16 B)
#define OFF_AH  0
#define OFF_AL  A_MAT
#define OFF_B   (2*A_MAT)           // [stage]
#define OFF_MB  (OFF_B + 2*B_MAT)   // 202752 ; full0,full1,empty0,empty1
#define SMEM_BYTES (OFF_MB + 32)

#define LOGC 1.3836465597893728f    // -log(0.1) - 0.5*log(2*pi)

__device__ __half g_Bh[NTPAD * KCDIM];

// ---------------------------------------------------------------------------
// Kernel 1: column-sums of nw, fp16 V_j (rows >= NTOP zero-filled)
// ---------------------------------------------------------------------------
__global__ void setup_kernel(const float* __restrict__ V,
                             const float* __restrict__ nw,
                             const float* __restrict__ noise,
                             float* __restrict__ out)
{
    __shared__ float s_part[8][32];
    __shared__ float s_sum[32];
    const int t   = threadIdx.x;
    const int b   = blockIdx.x;
    const int cl  = t & 31;
    const int rg  = t >> 5;
    const int col = b * 32 + cl;

    float s = 0.f;
    if (col < NTOP) {
        for (int i = rg; i < NTOP; i += 8)
            s += nw[i * NTOP + col];
    }
    s_part[rg][cl] = s;
    __syncthreads();
    if (rg == 0) {
        float v = s_part[0][cl];
        #pragma unroll
        for (int g = 1; g < 8; g++) v += s_part[g][cl];
        s_sum[cl] = v;
    }
    __syncthreads();

    for (int idx = t; idx < 32 * KCDIM; idx += 256) {
        int jl = idx >> 8;
        int k  = idx & 255;
        int jg = b * 32 + jl;                 // < 1024 (32 blocks)
        int g  = jg * KCDIM + k;
        float v = 0.f;
        if (jg < NTOP) v = fmaf(V[g], s_sum[jl], 0.1f * noise[g]);
        g_Bh[g] = __float2half_rn(v);
    }
    if (b == 0 && t == 0) *out = 0.f;
}

// ---------------------------------------------------------------------------
// helpers (base ISA: ldmatrix / mma.sync / cp.async / mbarrier)
// ---------------------------------------------------------------------------
__device__ __forceinline__ void ldsm4(uint32_t* r, uint32_t saddr) {
    asm volatile("ldmatrix.sync.aligned.m8n8.x4.shared.b16 {%0,%1,%2,%3}, [%4];\n"
                 : "=r"(r[0]), "=r"(r[1]), "=r"(r[2]), "=r"(r[3]) : "r"(saddr));
}
__device__ __forceinline__ void mma16816h(float* c, const uint32_t* a, uint32_t b0, uint32_t b1) {
    asm volatile(
        "mma.sync.aligned.m16n8k16.row.col.f32.f16.f16.f32 "
        "{%0,%1,%2,%3},{%4,%5,%6,%7},{%8,%9},{%0,%1,%2,%3};\n"
        : "+f"(c[0]), "+f"(c[1]), "+f"(c[2]), "+f"(c[3])
        : "r"(a[0]), "r"(a[1]), "r"(a[2]), "r"(a[3]), "r"(b0), "r"(b1));
}
__device__ __forceinline__ void cpasync16(uint32_t saddr, const void* g) {
    asm volatile("cp.async.cg.shared.global [%0], [%1], 16;\n" :: "r"(saddr), "l"(g));
}
__device__ __forceinline__ void mbar_wait(uint32_t mbar, uint32_t parity) {
    asm volatile(
        "{\n\t.reg .pred P;\n\t"
        "WL_%=:\n\t"
        "mbarrier.try_wait.parity.acquire.cta.shared::cta.b64 P, [%0], %1, 0x989680;\n\t"
        "@P bra WD_%=;\n\t"
        "bra WL_%=;\n\t"
        "WD_%=:\n\t}"
        :: "r"(mbar), "r"(parity) : "memory");
}
__device__ __forceinline__ void mbar_arrive(uint32_t mbar) {
    asm volatile("mbarrier.arrive.shared.b64 _, [%0];" :: "r"(mbar) : "memory");
}
__device__ __forceinline__ float sigmoidf(float x) {
    return __fdividef(1.f, 1.f + __expf(-x));
}
__device__ __forceinline__ uint32_t packh2(float a, float b) {
    __half2 p = __floats2half2_rn(a, b);
    return *(uint32_t*)&p;
}

// ---------------------------------------------------------------------------
// Kernel 2: warp-specialized fused kernel (fp16 x2 split GEMM).
// Consumers (warps 0-15): A fill, LDSM+MMA, epilogue. Warp tile 32x16.
// Producers (warps 16-19): cp.async B tiles into 2-stage ring w/ mbarriers.
// ---------------------------------------------------------------------------
__global__ void __launch_bounds__(NTHREADS, 1)
main_kernel(const float* __restrict__ R,
            const float* __restrict__ U,
            const float* __restrict__ W,
            const float* __restrict__ Bb,
            const int*   __restrict__ C,
            float* __restrict__ out)
{
    extern __shared__ __align__(16) char smem[];
    __shared__ float red[20];
    const uint32_t sb = (uint32_t)__cvta_generic_to_shared(smem);
    const uint32_t mb_full  = sb + OFF_MB;        // +0, +8
    const uint32_t mb_empty = sb + OFF_MB + 16;   // +0, +8

    const int tid  = threadIdx.x;
    const int lane = tid & 31;
    const int warp = tid >> 5;
    const int rowbase = blockIdx.x * BM;          // 313 CTAs; last covers rows >= TLTOT

    if (tid == 0) {
        asm volatile("mbarrier.init.shared.b64 [%0], %1;" :: "r"(mb_full),      "r"(128u) : "memory");
        asm volatile("mbarrier.init.shared.b64 [%0], %1;" :: "r"(mb_full + 8),  "r"(128u) : "memory");
        asm volatile("mbarrier.init.shared.b64 [%0], %1;" :: "r"(mb_empty),     "r"(512u) : "memory");
        asm volatile("mbarrier.init.shared.b64 [%0], %1;" :: "r"(mb_empty + 8), "r"(512u) : "memory");
    }
    __syncthreads();   // mbars initialized

    float lsum = 0.f;

    if (warp >= 16) {
        // ================= PRODUCER (4 warps, 128 threads) =================
        const int ptid = tid - NCTHREADS;
        for (int t = 0; t < NT; t++) {
            const int s = t & 1;
            const uint32_t pp = (((uint32_t)t >> 1) & 1u) ^ 1u;   // first waits pass
            mbar_wait(mb_empty + s * 8, pp);
            const int j0 = t * BN;
            const uint32_t dbase = sb + OFF_B + (uint32_t)s * B_MAT;
            #pragma unroll
            for (int i = 0; i < 16; i++) {
                int c  = i * 128 + ptid;        // 0..2047
                int n  = c >> 5;                // 0..63
                int c8 = c & 31;                // k-chunk of 8 halfs
                const __half* src = g_Bh + (size_t)(j0 + n) * KCDIM + c8 * 8;
                cpasync16(dbase + (uint32_t)(n * PITCH + c8 * 8) * 2, src);
            }
            asm volatile("cp.async.commit_group;\n" ::: "memory");
            asm volatile("cp.async.wait_group 0;\n" ::: "memory");
            mbar_arrive(mb_full + s * 8);
        }
    } else {
        // ================= CONSUMER (16 warps, 512 threads) =================
        const int wm = warp & 3;     // 4 over M (32 rows)
        const int wn = warp >> 2;    // 4 over N (16 cols)

        // ---- A fill: U_emb -> fp16 split (hi/lo) ----
        {
            const float w0 = W[0], w1 = W[1], w2 = W[2], w3 = W[3], w4 = W[4];
            const float bb = Bb[0];
            __half* Ah = (__half*)(smem + OFF_AH);
            __half* Al = (__half*)(smem + OFF_AL);
            #pragma unroll
            for (int i = 0; i < (BM * (KCDIM / 4)) / NCTHREADS; i++) {   // 16 iters
                int idx = tid + i * NCTHREADS;
                int r  = idx >> 6;          // 0..127
                int k0 = (idx & 63) * 4;
                float o[4], ol[4];
                int gr = rowbase + r;
                if (gr < TLTOT) {
                    const float4* up = (const float4*)(U + ((size_t)gr * (KCDIM * 5) + (size_t)k0 * 5));
                    float4 f0 = __ldcs(up + 0);
                    float4 f1 = __ldcs(up + 1);
                    float4 f2 = __ldcs(up + 2);
                    float4 f3 = __ldcs(up + 3);
                    float4 f4 = __ldcs(up + 4);
                    const float f[20] = {f0.x,f0.y,f0.z,f0.w, f1.x,f1.y,f1.z,f1.w,
                                         f2.x,f2.y,f2.z,f2.w, f3.x,f3.y,f3.z,f3.w,
                                         f4.x,f4.y,f4.z,f4.w};
                    #pragma unroll
                    for (int q = 0; q < 4; q++) {
                        float v = bb;
                        v = fmaf(f[q*5+0], w0, v);
                        v = fmaf(f[q*5+1], w1, v);
                        v = fmaf(f[q*5+2], w2, v);
                        v = fmaf(f[q*5+3], w3, v);
                        v = fmaf(f[q*5+4], w4, v);
                        o[q]  = v;
                        ol[q] = v - __half2float(__float2half_rn(v));
                    }
                } else {
                    #pragma unroll
                    for (int q = 0; q < 4; q++) { o[q] = 0.f; ol[q] = 0.f; }
                }
                *(uint2*)(Ah + r * PITCH + k0) = make_uint2(packh2(o[0], o[1]),  packh2(o[2], o[3]));
                *(uint2*)(Al + r * PITCH + k0) = make_uint2(packh2(ol[0], ol[1]), packh2(ol[2], ol[3]));
            }
        }
        asm volatile("bar.sync 1, %0;" :: "n"(NCTHREADS) : "memory");   // consumers only

        // ldmatrix lane addresses (bytes)
        const uint32_t arow = (uint32_t)((wm * 32 + (lane & 15)) * PITCH + (lane >> 4) * 8) * 2;
        const uint32_t boff = (uint32_t)((wn * 16 + ((lane >> 4) & 1) * 8 + (lane & 7)) * PITCH
                               + ((lane >> 3) & 1) * 8) * 2;
        const uint32_t sAh = sb + OFF_AH, sAl = sb + OFF_AL;
        const uint32_t aStep = (uint32_t)(16 * PITCH) * 2;   // +16 rows

        // epilogue coords: rows rowbase+wm*32+(lane>>2)+mi*16+rr*8 ; cols j0+wn*16+ni*8+(lane&3)*2
        const int er0 = rowbase + wm * 32 + (lane >> 2);
        const int ejc = wn * 16 + ((lane & 3) << 1);

        for (int t = 0; t < NT; t++) {
            const int s = t & 1;
            const uint32_t pc = ((uint32_t)t >> 1) & 1u;
            const int j0 = t * BN;

            // ---- prefetch R/C (DRAM latency overlaps full-wait + MMA) ----
            float2 rv[4][2];
            int2   cvv[4][2];
            #pragma unroll
            for (int mi = 0; mi < 2; mi++) {
                #pragma unroll
                for (int rr = 0; rr < 2; rr++) {
                    const int row = er0 + mi * 16 + rr * 8;
                    #pragma unroll
                    for (int ni = 0; ni < 2; ni++) {
                        cvv[mi*2+rr][ni] = make_int2(0, 0);
                        const int jc = j0 + ejc + ni * 8;
                        if (row < TLTOT && jc < NTOP) {
                            const size_t off = (size_t)row * NTOP + jc;
                            rv[mi*2+rr][ni]  = __ldcs((const float2*)(R + off));
                            cvv[mi*2+rr][ni] = __ldcs((const int2*)(C + off));
                        }
                    }
                }
            }

            mbar_wait(mb_full + s * 8, pc);

            // ---- MMA: acc = Ah*B + Al*B  (fp16 x2 split) ----
            const uint32_t sB = sb + OFF_B + (uint32_t)s * B_MAT;
            float acc[2][2][4] = {};
            #pragma unroll 4
            for (int ks = 0; ks < 16; ks++) {
                const uint32_t k0b = (uint32_t)(ks * 16) * 2;
                uint32_t ah0[4], ah1[4], al0[4], al1[4], b[4];
                ldsm4(ah0, sAh + arow + k0b);
                ldsm4(ah1, sAh + arow + aStep + k0b);
                ldsm4(al0, sAl + arow + k0b);
                ldsm4(al1, sAl + arow + aStep + k0b);
                ldsm4(b,   sB  + boff + k0b);
                #pragma unroll
                for (int ni = 0; ni < 2; ni++) {
                    const int s2 = ni * 2;
                    mma16816h(acc[0][ni], ah0, b[s2], b[s2 + 1]);
                    mma16816h(acc[0][ni], al0, b[s2], b[s2 + 1]);
                    mma16816h(acc[1][ni], ah1, b[s2], b[s2 + 1]);
                    mma16816h(acc[1][ni], al1, b[s2], b[s2 + 1]);
                }
            }
            mbar_arrive(mb_empty + s * 8);   // free stage before epilogue math

            // ---- epilogue ----
            #pragma unroll
            for (int mi = 0; mi < 2; mi++) {
                #pragma unroll
                for (int ni = 0; ni < 2; ni++) {
                    #pragma unroll
                    for (int rr = 0; rr < 2; rr++) {
                        const float2 r2 = rv[mi*2+rr][ni];
                        const int2   c2 = cvv[mi*2+rr][ni];
                        if (c2.x == 1) { float m = sigmoidf(acc[mi][ni][rr*2+0]); float z = (r2.x - m) * 10.f; lsum += LOGC - 0.5f * z * z; }
                        if (c2.y == 1) { float m = sigmoidf(acc[mi][ni][rr*2+1]); float z = (r2.y - m) * 10.f; lsum += LOGC - 0.5f * z * z; }
                    }
                }
            }
        }
    }

    // ---- block reduction (producers contribute 0) ----
    #pragma unroll
    for (int o = 16; o > 0; o >>= 1)
        lsum += __shfl_xor_sync(0xFFFFFFFFu, lsum, o);
    if (lane == 0) red[warp] = lsum;
    __syncthreads();
    if (warp == 0) {
        float v = (lane < 20) ? red[lane] : 0.f;
        #pragma unroll
        for (int o = 16; o > 0; o >>= 1)
            v += __shfl_xor_sync(0xFFFFFFFFu, v, o);
        if (lane == 0) atomicAdd(out, v);
    }
}

// ---------------------------------------------------------------------------
extern "C" void kernel_launch(void* const* d_in, const int* in_sizes, int n_in,
                              void* d_out, int out_size)
{
    // Identify inputs by element count (dict order breaks ties:
    // V before noise at 256000, R before C at 40000000).
    const float *V = nullptr, *R = nullptr, *nw = nullptr, *U = nullptr;
    const float *W = nullptr, *Bb = nullptr, *noise = nullptr;
    const int* C = nullptr;
    int seen256k = 0, seen40m = 0;
    for (int i = 0; i < n_in; i++) {
        switch (in_sizes[i]) {
            case 256000:
                if (seen256k++ == 0) V = (const float*)d_in[i];
                else                 noise = (const float*)d_in[i];
                break;
            case 40000000:
                if (seen40m++ == 0) R = (const float*)d_in[i];
                else                C = (const int*)d_in[i];
                break;
            case 1000000:  nw = (const float*)d_in[i]; break;
            case 51200000: U  = (const float*)d_in[i]; break;
            case 5:        W  = (const float*)d_in[i]; break;
            case 1:        Bb = (const float*)d_in[i]; break;
            default: break; // Q unused
        }
    }
    float* out = (float*)d_out;

    cudaFuncSetAttribute(main_kernel, cudaFuncAttributeMaxDynamicSharedMemorySize, SMEM_BYTES);

    setup_kernel<<<32, 256>>>(V, nw, noise, out);
    main_kernel<<<(TLTOT + BM - 1) / BM, NTHREADS, SMEM_BYTES>>>(R, U, W, Bb, C, out);
}

// round 15
// speedup vs baseline: 1.9069x; 1.4127x over previous
#include <cuda_runtime.h>
#include <cuda_fp16.h>
#include <cstdint>

#define TLTOT 40000
#define NTOP  1000
#define NTPAD 1024          // g_B rows padded: tail tile reads zeros, no guards
#define KCDIM 256
#define BM    64
#define BN    64
#define NT    16            // 1024/64 j-tiles (tail zero-padded)
#define PITCH 264           // fp16 per A/B SMEM row (256+8 pad, LDSM conflict-free)
#define RCP   72            // floats per staged R/C row
#define NTHREADS 640        // 16 consumer warps + 4 producer warps
#define NCTHREADS 512

#define A_MAT   (BM*PITCH*2)            // 33792
#define B_MAT   (BN*PITCH*2)            // 33792
#define RC_MAT  (BM*RCP*4)              // 18432
#define OFF_AH  0
#define OFF_AL  A_MAT
#define OFF_B   (2*A_MAT)               // [stage]
#define OFF_R   (OFF_B + 2*B_MAT)       // [stage]
#define OFF_C   (OFF_R + 2*RC_MAT)      // [stage]
#define OFF_MB  (OFF_C + 2*RC_MAT)      // 208896 ; full0,full1,empty0,empty1
#define SMEM_BYTES (OFF_MB + 32)        // 208928 (<= 227KB cap)

#define LOGC 1.3836465597893728f        // -log(0.1) - 0.5*log(2*pi)

__device__ __half g_Bh[NTPAD * KCDIM];

// ---------------------------------------------------------------------------
// Kernel 1: column-sums of nw, fp16 V_j (rows >= NTOP zero-filled)
// ---------------------------------------------------------------------------
__global__ void setup_kernel(const float* __restrict__ V,
                             const float* __restrict__ nw,
                             const float* __restrict__ noise,
                             float* __restrict__ out)
{
    __shared__ float s_part[8][32];
    __shared__ float s_sum[32];
    const int t   = threadIdx.x;
    const int b   = blockIdx.x;
    const int cl  = t & 31;
    const int rg  = t >> 5;
    const int col = b * 32 + cl;

    float s = 0.f;
    if (col < NTOP) {
        for (int i = rg; i < NTOP; i += 8)
            s += nw[i * NTOP + col];
    }
    s_part[rg][cl] = s;
    __syncthreads();
    if (rg == 0) {
        float v = s_part[0][cl];
        #pragma unroll
        for (int g = 1; g < 8; g++) v += s_part[g][cl];
        s_sum[cl] = v;
    }
    __syncthreads();

    for (int idx = t; idx < 32 * KCDIM; idx += 256) {
        int jl = idx >> 8;
        int k  = idx & 255;
        int jg = b * 32 + jl;                 // < 1024 (32 blocks)
        int g  = jg * KCDIM + k;
        float v = 0.f;
        if (jg < NTOP) v = fmaf(V[g], s_sum[jl], 0.1f * noise[g]);
        g_Bh[g] = __float2half_rn(v);
    }
    if (b == 0 && t == 0) *out = 0.f;
}

// ---------------------------------------------------------------------------
// helpers
// ---------------------------------------------------------------------------
__device__ __forceinline__ void ldsm4(uint32_t* r, uint32_t saddr) {
    asm volatile("ldmatrix.sync.aligned.m8n8.x4.shared.b16 {%0,%1,%2,%3}, [%4];\n"
                 : "=r"(r[0]), "=r"(r[1]), "=r"(r[2]), "=r"(r[3]) : "r"(saddr));
}
__device__ __forceinline__ void mma16816h(float* c, const uint32_t* a, uint32_t b0, uint32_t b1) {
    asm volatile(
        "mma.sync.aligned.m16n8k16.row.col.f32.f16.f16.f32 "
        "{%0,%1,%2,%3},{%4,%5,%6,%7},{%8,%9},{%0,%1,%2,%3};\n"
        : "+f"(c[0]), "+f"(c[1]), "+f"(c[2]), "+f"(c[3])
        : "r"(a[0]), "r"(a[1]), "r"(a[2]), "r"(a[3]), "r"(b0), "r"(b1));
}
__device__ __forceinline__ void cpasync16(uint32_t saddr, const void* g) {
    asm volatile("cp.async.cg.shared.global [%0], [%1], 16;\n" :: "r"(saddr), "l"(g));
}
__device__ __forceinline__ void mbar_wait(uint32_t mbar, uint32_t parity) {
    asm volatile(
        "{\n\t.reg .pred P;\n\t"
        "WL_%=:\n\t"
        "mbarrier.try_wait.parity.acquire.cta.shared::cta.b64 P, [%0], %1, 0x989680;\n\t"
        "@P bra WD_%=;\n\t"
        "bra WL_%=;\n\t"
        "WD_%=:\n\t}"
        :: "r"(mbar), "r"(parity) : "memory");
}
__device__ __forceinline__ void mbar_arrive(uint32_t mbar) {
    asm volatile("mbarrier.arrive.shared.b64 _, [%0];" :: "r"(mbar) : "memory");
}
__device__ __forceinline__ float sigmoidf(float x) {
    return __fdividef(1.f, 1.f + __expf(-x));
}
__device__ __forceinline__ uint32_t packh2(float a, float b) {
    __half2 p = __floats2half2_rn(a, b);
    return *(uint32_t*)&p;
}

// ---------------------------------------------------------------------------
// Kernel 2: warp-specialized; producers stage B *and* R/C, consumers never
// touch global memory in the mainloop (pure LDS + HMMA + math).
// ---------------------------------------------------------------------------
__global__ void __launch_bounds__(NTHREADS, 1)
main_kernel(const float* __restrict__ R,
            const float* __restrict__ U,
            const float* __restrict__ W,
            const float* __restrict__ Bb,
            const int*   __restrict__ C,
            float* __restrict__ out)
{
    extern __shared__ __align__(16) char smem[];
    __shared__ float red[20];
    const uint32_t sb = (uint32_t)__cvta_generic_to_shared(smem);
    const uint32_t mb_full  = sb + OFF_MB;        // +0, +8
    const uint32_t mb_empty = sb + OFF_MB + 16;   // +0, +8

    const int tid  = threadIdx.x;
    const int lane = tid & 31;
    const int warp = tid >> 5;
    const int rowbase = blockIdx.x * BM;          // 625*64 = 40000 exact

    if (tid == 0) {
        asm volatile("mbarrier.init.shared.b64 [%0], %1;" :: "r"(mb_full),      "r"(128u) : "memory");
        asm volatile("mbarrier.init.shared.b64 [%0], %1;" :: "r"(mb_full + 8),  "r"(128u) : "memory");
        asm volatile("mbarrier.init.shared.b64 [%0], %1;" :: "r"(mb_empty),     "r"(512u) : "memory");
        asm volatile("mbarrier.init.shared.b64 [%0], %1;" :: "r"(mb_empty + 8), "r"(512u) : "memory");
    }
    __syncthreads();   // mbars initialized

    float lsum = 0.f;

    if (warp >= 16) {
        // ================= PRODUCER (4 warps, 128 threads) =================
        const int ptid = tid - NCTHREADS;
        for (int t = 0; t < NT; t++) {
            const int s = t & 1;
            const uint32_t pp = (((uint32_t)t >> 1) & 1u) ^ 1u;   // first waits pass
            mbar_wait(mb_empty + s * 8, pp);
            const int j0 = t * BN;

            // ---- B tile: 2048 chunks ----
            {
                const uint32_t dbase = sb + OFF_B + (uint32_t)s * B_MAT;
                #pragma unroll
                for (int i = 0; i < 16; i++) {
                    int c  = i * 128 + ptid;        // 0..2047
                    int n  = c >> 5;                // 0..63
                    int c8 = c & 31;
                    cpasync16(dbase + (uint32_t)(n * PITCH + c8 * 8) * 2,
                              g_Bh + (size_t)(j0 + n) * KCDIM + c8 * 8);
                }
            }
            // ---- R and C tiles: 1024 chunks each ----
            {
                const uint32_t rbase = sb + OFF_R + (uint32_t)s * RC_MAT;
                const uint32_t cbase = sb + OFF_C + (uint32_t)s * RC_MAT;
                #pragma unroll
                for (int i = 0; i < 8; i++) {
                    int c   = i * 128 + ptid;       // 0..1023
                    int row = c >> 4;               // 0..63
                    int c4  = c & 15;               // col group of 4
                    if (j0 + c4 * 4 < NTOP) {       // chunks never straddle 1000
                        const size_t goff = (size_t)(rowbase + row) * NTOP + j0 + c4 * 4;
                        const uint32_t so = (uint32_t)(row * RCP + c4 * 4) * 4;
                        cpasync16(rbase + so, R + goff);
                        cpasync16(cbase + so, C + goff);
                    }
                }
            }
            asm volatile("cp.async.commit_group;\n" ::: "memory");
            asm volatile("cp.async.wait_group 0;\n" ::: "memory");
            mbar_arrive(mb_full + s * 8);
        }
    } else {
        // ================= CONSUMER (16 warps, 512 threads) =================
        const int wm = warp & 3;     // 4 over M (16 rows)
        const int wn = warp >> 2;    // 4 over N (16 cols)

        // ---- A fill: U_emb -> fp16 split (hi/lo) ----
        {
            const float w0 = W[0], w1 = W[1], w2 = W[2], w3 = W[3], w4 = W[4];
            const float bb = Bb[0];
            __half* Ah = (__half*)(smem + OFF_AH);
            __half* Al = (__half*)(smem + OFF_AL);
            #pragma unroll
            for (int i = 0; i < (BM * (KCDIM / 4)) / NCTHREADS; i++) {   // 8 iters
                int idx = tid + i * NCTHREADS;
                int r  = idx >> 6;          // 0..63
                int k0 = (idx & 63) * 4;
                const float4* up = (const float4*)(U + ((size_t)(rowbase + r) * (KCDIM * 5) + (size_t)k0 * 5));
                float4 f0 = __ldcs(up + 0);
                float4 f1 = __ldcs(up + 1);
                float4 f2 = __ldcs(up + 2);
                float4 f3 = __ldcs(up + 3);
                float4 f4 = __ldcs(up + 4);
                const float f[20] = {f0.x,f0.y,f0.z,f0.w, f1.x,f1.y,f1.z,f1.w,
                                     f2.x,f2.y,f2.z,f2.w, f3.x,f3.y,f3.z,f3.w,
                                     f4.x,f4.y,f4.z,f4.w};
                float o[4], ol[4];
                #pragma unroll
                for (int q = 0; q < 4; q++) {
                    float v = bb;
                    v = fmaf(f[q*5+0], w0, v);
                    v = fmaf(f[q*5+1], w1, v);
                    v = fmaf(f[q*5+2], w2, v);
                    v = fmaf(f[q*5+3], w3, v);
                    v = fmaf(f[q*5+4], w4, v);
                    o[q]  = v;
                    ol[q] = v - __half2float(__float2half_rn(v));
                }
                *(uint2*)(Ah + r * PITCH + k0) = make_uint2(packh2(o[0], o[1]),  packh2(o[2], o[3]));
                *(uint2*)(Al + r * PITCH + k0) = make_uint2(packh2(ol[0], ol[1]), packh2(ol[2], ol[3]));
            }
        }
        asm volatile("bar.sync 1, %0;" :: "n"(NCTHREADS) : "memory");   // consumers only

        // ldmatrix lane addresses (bytes)
        const uint32_t arow = (uint32_t)((wm * 16 + (lane & 15)) * PITCH + (lane >> 4) * 8) * 2;
        const uint32_t boff = (uint32_t)((wn * 16 + ((lane >> 4) & 1) * 8 + (lane & 7)) * PITCH
                               + ((lane >> 3) & 1) * 8) * 2;
        const uint32_t sAh = sb + OFF_AH, sAl = sb + OFF_AL;

        // epilogue coords (SMEM-local)
        const int er  = wm * 16 + (lane >> 2);      // rows er, er+8
        const int ejc = wn * 16 + ((lane & 3) << 1);
        const float* sR = (const float*)(smem + OFF_R);
        const int*   sC = (const int*)(smem + OFF_C);

        for (int t = 0; t < NT; t++) {
            const int s = t & 1;
            const uint32_t pc = ((uint32_t)t >> 1) & 1u;
            const int j0 = t * BN;

            mbar_wait(mb_full + s * 8, pc);

            // ---- MMA: acc = Ah*B + Al*B (fp16 x2 split) ----
            const uint32_t sB = sb + OFF_B + (uint32_t)s * B_MAT;
            float acc[2][4] = {};
            #pragma unroll 4
            for (int ks = 0; ks < 16; ks++) {
                const uint32_t k0b = (uint32_t)(ks * 16) * 2;
                uint32_t ah[4], al[4], b[4];
                ldsm4(ah, sAh + arow + k0b);
                ldsm4(al, sAl + arow + k0b);
                ldsm4(b,  sB  + boff + k0b);
                mma16816h(acc[0], ah, b[0], b[1]);
                mma16816h(acc[1], ah, b[2], b[3]);
                mma16816h(acc[0], al, b[0], b[1]);
                mma16816h(acc[1], al, b[2], b[3]);
            }

            // ---- epilogue from staged SMEM ----
            const int sro = s * (RC_MAT / 4);
            #pragma unroll
            for (int ni = 0; ni < 2; ni++) {
                const int jc = ejc + ni * 8;
                if (j0 + jc < NTOP) {
                    #pragma unroll
                    for (int rr = 0; rr < 2; rr++) {
                        const int so = sro + (er + rr * 8) * RCP + jc;
                        float2 r2 = *(const float2*)(sR + so);
                        int2   c2 = *(const int2*)(sC + so);
                        if (c2.x == 1) { float m = sigmoidf(acc[ni][rr*2+0]); float z = (r2.x - m) * 10.f; lsum += LOGC - 0.5f * z * z; }
                        if (c2.y == 1) { float m = sigmoidf(acc[ni][rr*2+1]); float z = (r2.y - m) * 10.f; lsum += LOGC - 0.5f * z * z; }
                    }
                }
            }
            mbar_arrive(mb_empty + s * 8);   // stage free (B + R/C consumed)
        }
    }

    // ---- block reduction (producers contribute 0) ----
    #pragma unroll
    for (int o = 16; o > 0; o >>= 1)
        lsum += __shfl_xor_sync(0xFFFFFFFFu, lsum, o);
    if (lane == 0) red[warp] = lsum;
    __syncthreads();
    if (warp == 0) {
        float v = (lane < 20) ? red[lane] : 0.f;
        #pragma unroll
        for (int o = 16; o > 0; o >>= 1)
            v += __shfl_xor_sync(0xFFFFFFFFu, v, o);
        if (lane == 0) atomicAdd(out, v);
    }
}

// ---------------------------------------------------------------------------
extern "C" void kernel_launch(void* const* d_in, const int* in_sizes, int n_in,
                              void* d_out, int out_size)
{
    // Identify inputs by element count (dict order breaks ties:
    // V before noise at 256000, R before C at 40000000).
    const float *V = nullptr, *R = nullptr, *nw = nullptr, *U = nullptr;
    const float *W = nullptr, *Bb = nullptr, *noise = nullptr;
    const int* C = nullptr;
    int seen256k = 0, seen40m = 0;
    for (int i = 0; i < n_in; i++) {
        switch (in_sizes[i]) {
            case 256000:
                if (seen256k++ == 0) V = (const float*)d_in[i];
                else                 noise = (const float*)d_in[i];
                break;
            case 40000000:
                if (seen40m++ == 0) R = (const float*)d_in[i];
                else                C = (const int*)d_in[i];
                break;
            case 1000000:  nw = (const float*)d_in[i]; break;
            case 51200000: U  = (const float*)d_in[i]; break;
            case 5:        W  = (const float*)d_in[i]; break;
            case 1:        Bb = (const float*)d_in[i]; break;
            default: break; // Q unused
        }
    }
    float* out = (float*)d_out;

    cudaFuncSetAttribute(main_kernel, cudaFuncAttributeMaxDynamicSharedMemorySize, SMEM_BYTES);

    setup_kernel<<<32, 256>>>(V, nw, noise, out);
    main_kernel<<<TLTOT / BM, NTHREADS, SMEM_BYTES>>>(R, U, W, Bb, C, out);
}

// round 16
// speedup vs baseline: 2.6769x; 1.4038x over previous
#include <cuda_runtime.h>
#include <cuda_fp16.h>
#include <cstdint>

#define TLTOT 40000
#define NTOP  1000
#define NTPAD 1024          // g_B rows padded: tail tile reads zeros, no guards
#define KCDIM 256
#define BM    64
#define BN    64
#define NT    16            // 1024/64 j-tiles (tail zero-padded)
#define PITCH 264           // fp16 per A/B SMEM row (256+8 pad, LDSM conflict-free)
#define RCP   68            // floats per staged R/C row
#define NTHREADS 640        // 16 consumer warps + 4 producer warps
#define NCTHREADS 512

#define A_MAT   (BM*PITCH*2)            // 33792 (single fp16 A)
#define B_MAT   (BN*PITCH*2)            // 33792 (single fp16 B)
#define RC_MAT  (BM*RCP*4)              // 17408
#define OFF_A   0
#define OFF_B   A_MAT                   // [stage]
#define OFF_R   (OFF_B + 2*B_MAT)       // [stage]
#define OFF_C   (OFF_R + 2*RC_MAT)      // [stage]
#define OFF_MB  (OFF_C + 2*RC_MAT)      // 171008 ; fullB0,fullB1,fullRC0,fullRC1,empty0,empty1
#define SMEM_BYTES (OFF_MB + 48)

#define LOGC 1.3836465597893728f        // -log(0.1) - 0.5*log(2*pi)

__device__ __half g_Bh[NTPAD * KCDIM];

// ---------------------------------------------------------------------------
// Kernel 1: column-sums of nw, fp16 V_j (rows >= NTOP zero-filled)
// ---------------------------------------------------------------------------
__global__ void setup_kernel(const float* __restrict__ V,
                             const float* __restrict__ nw,
                             const float* __restrict__ noise,
                             float* __restrict__ out)
{
    __shared__ float s_part[8][32];
    __shared__ float s_sum[32];
    const int t   = threadIdx.x;
    const int b   = blockIdx.x;
    const int cl  = t & 31;
    const int rg  = t >> 5;
    const int col = b * 32 + cl;

    float s = 0.f;
    if (col < NTOP) {
        for (int i = rg; i < NTOP; i += 8)
            s += nw[i * NTOP + col];
    }
    s_part[rg][cl] = s;
    __syncthreads();
    if (rg == 0) {
        float v = s_part[0][cl];
        #pragma unroll
        for (int g = 1; g < 8; g++) v += s_part[g][cl];
        s_sum[cl] = v;
    }
    __syncthreads();

    for (int idx = t; idx < 32 * KCDIM; idx += 256) {
        int jl = idx >> 8;
        int k  = idx & 255;
        int jg = b * 32 + jl;                 // < 1024 (32 blocks)
        int g  = jg * KCDIM + k;
        float v = 0.f;
        if (jg < NTOP) v = fmaf(V[g], s_sum[jl], 0.1f * noise[g]);
        g_Bh[g] = __float2half_rn(v);
    }
    if (b == 0 && t == 0) *out = 0.f;
}

// ---------------------------------------------------------------------------
// helpers
// ---------------------------------------------------------------------------
__device__ __forceinline__ void ldsm4(uint32_t* r, uint32_t saddr) {
    asm volatile("ldmatrix.sync.aligned.m8n8.x4.shared.b16 {%0,%1,%2,%3}, [%4];\n"
                 : "=r"(r[0]), "=r"(r[1]), "=r"(r[2]), "=r"(r[3]) : "r"(saddr));
}
__device__ __forceinline__ void mma16816h(float* c, const uint32_t* a, uint32_t b0, uint32_t b1) {
    asm volatile(
        "mma.sync.aligned.m16n8k16.row.col.f32.f16.f16.f32 "
        "{%0,%1,%2,%3},{%4,%5,%6,%7},{%8,%9},{%0,%1,%2,%3};\n"
        : "+f"(c[0]), "+f"(c[1]), "+f"(c[2]), "+f"(c[3])
        : "r"(a[0]), "r"(a[1]), "r"(a[2]), "r"(a[3]), "r"(b0), "r"(b1));
}
__device__ __forceinline__ void cpasync16(uint32_t saddr, const void* g) {
    asm volatile("cp.async.cg.shared.global [%0], [%1], 16;\n" :: "r"(saddr), "l"(g));
}
__device__ __forceinline__ void mbar_wait(uint32_t mbar, uint32_t parity) {
    asm volatile(
        "{\n\t.reg .pred P;\n\t"
        "WL_%=:\n\t"
        "mbarrier.try_wait.parity.acquire.cta.shared::cta.b64 P, [%0], %1, 0x989680;\n\t"
        "@P bra WD_%=;\n\t"
        "bra WL_%=;\n\t"
        "WD_%=:\n\t}"
        :: "r"(mbar), "r"(parity) : "memory");
}
__device__ __forceinline__ void mbar_arrive(uint32_t mbar) {
    asm volatile("mbarrier.arrive.shared.b64 _, [%0];" :: "r"(mbar) : "memory");
}
__device__ __forceinline__ float sigmoidf(float x) {
    return __fdividef(1.f, 1.f + __expf(-x));
}
__device__ __forceinline__ uint32_t packh2(float a, float b) {
    __half2 p = __floats2half2_rn(a, b);
    return *(uint32_t*)&p;
}

// ---------------------------------------------------------------------------
// Kernel 2: warp-specialized, pure-fp16 GEMM.
// Producers stage B then R/C (split commits, separate full-bars) so MMA
// starts as soon as B lands. Consumers: pure LDS + HMMA + math.
// ---------------------------------------------------------------------------
__global__ void __launch_bounds__(NTHREADS, 1)
main_kernel(const float* __restrict__ R,
            const float* __restrict__ U,
            const float* __restrict__ W,
            const float* __restrict__ Bb,
            const int*   __restrict__ C,
            float* __restrict__ out)
{
    extern __shared__ __align__(16) char smem[];
    __shared__ float red[20];
    const uint32_t sb = (uint32_t)__cvta_generic_to_shared(smem);
    const uint32_t mb_fullB  = sb + OFF_MB;        // +0, +8
    const uint32_t mb_fullRC = sb + OFF_MB + 16;   // +0, +8
    const uint32_t mb_empty  = sb + OFF_MB + 32;   // +0, +8

    const int tid  = threadIdx.x;
    const int lane = tid & 31;
    const int warp = tid >> 5;
    const int rowbase = blockIdx.x * BM;           // 625*64 = 40000 exact

    if (tid == 0) {
        asm volatile("mbarrier.init.shared.b64 [%0], %1;" :: "r"(mb_fullB),       "r"(128u) : "memory");
        asm volatile("mbarrier.init.shared.b64 [%0], %1;" :: "r"(mb_fullB + 8),   "r"(128u) : "memory");
        asm volatile("mbarrier.init.shared.b64 [%0], %1;" :: "r"(mb_fullRC),      "r"(128u) : "memory");
        asm volatile("mbarrier.init.shared.b64 [%0], %1;" :: "r"(mb_fullRC + 8),  "r"(128u) : "memory");
        asm volatile("mbarrier.init.shared.b64 [%0], %1;" :: "r"(mb_empty),       "r"(512u) : "memory");
        asm volatile("mbarrier.init.shared.b64 [%0], %1;" :: "r"(mb_empty + 8),   "r"(512u) : "memory");
    }
    __syncthreads();   // mbars initialized

    float lsum = 0.f;

    if (warp >= 16) {
        // ================= PRODUCER (4 warps, 128 threads) =================
        const int ptid = tid - NCTHREADS;
        for (int t = 0; t < NT; t++) {
            const int s = t & 1;
            const uint32_t pp = (((uint32_t)t >> 1) & 1u) ^ 1u;   // first waits pass
            mbar_wait(mb_empty + s * 8, pp);
            const int j0 = t * BN;

            // ---- group 1: B tile (2048 x 16B) ----
            {
                const uint32_t dbase = sb + OFF_B + (uint32_t)s * B_MAT;
                #pragma unroll
                for (int i = 0; i < 16; i++) {
                    int c  = i * 128 + ptid;        // 0..2047
                    int n  = c >> 5;                // 0..63
                    int c8 = c & 31;
                    cpasync16(dbase + (uint32_t)(n * PITCH + c8 * 8) * 2,
                              g_Bh + (size_t)(j0 + n) * KCDIM + c8 * 8);
                }
            }
            asm volatile("cp.async.commit_group;\n" ::: "memory");

            // ---- group 2: R and C tiles (1024 x 16B each) ----
            {
                const uint32_t rbase = sb + OFF_R + (uint32_t)s * RC_MAT;
                const uint32_t cbase = sb + OFF_C + (uint32_t)s * RC_MAT;
                #pragma unroll
                for (int i = 0; i < 8; i++) {
                    int c   = i * 128 + ptid;       // 0..1023
                    int row = c >> 4;               // 0..63
                    int c4  = c & 15;               // col group of 4
                    if (j0 + c4 * 4 < NTOP) {       // chunks never straddle 1000
                        const size_t goff = (size_t)(rowbase + row) * NTOP + j0 + c4 * 4;
                        const uint32_t so = (uint32_t)(row * RCP + c4 * 4) * 4;
                        cpasync16(rbase + so, R + goff);
                        cpasync16(cbase + so, C + goff);
                    }
                }
            }
            asm volatile("cp.async.commit_group;\n" ::: "memory");

            asm volatile("cp.async.wait_group 1;\n" ::: "memory");   // B landed
            mbar_arrive(mb_fullB + s * 8);
            asm volatile("cp.async.wait_group 0;\n" ::: "memory");   // R/C landed
            mbar_arrive(mb_fullRC + s * 8);
        }
    } else {
        // ================= CONSUMER (16 warps, 512 threads) =================
        const int wm = warp & 3;     // 4 over M (16 rows)
        const int wn = warp >> 2;    // 4 over N (16 cols)

        // ---- A fill: U_emb -> single fp16 ----
        {
            const float w0 = W[0], w1 = W[1], w2 = W[2], w3 = W[3], w4 = W[4];
            const float bb = Bb[0];
            __half* A = (__half*)(smem + OFF_A);
            #pragma unroll
            for (int i = 0; i < (BM * (KCDIM / 4)) / NCTHREADS; i++) {   // 8 iters
                int idx = tid + i * NCTHREADS;
                int r  = idx >> 6;          // 0..63
                int k0 = (idx & 63) * 4;
                const float4* up = (const float4*)(U + ((size_t)(rowbase + r) * (KCDIM * 5) + (size_t)k0 * 5));
                float4 f0 = __ldcs(up + 0);
                float4 f1 = __ldcs(up + 1);
                float4 f2 = __ldcs(up + 2);
                float4 f3 = __ldcs(up + 3);
                float4 f4 = __ldcs(up + 4);
                const float f[20] = {f0.x,f0.y,f0.z,f0.w, f1.x,f1.y,f1.z,f1.w,
                                     f2.x,f2.y,f2.z,f2.w, f3.x,f3.y,f3.z,f3.w,
                                     f4.x,f4.y,f4.z,f4.w};
                float o[4];
                #pragma unroll
                for (int q = 0; q < 4; q++) {
                    float v = bb;
                    v = fmaf(f[q*5+0], w0, v);
                    v = fmaf(f[q*5+1], w1, v);
                    v = fmaf(f[q*5+2], w2, v);
                    v = fmaf(f[q*5+3], w3, v);
                    v = fmaf(f[q*5+4], w4, v);
                    o[q] = v;
                }
                *(uint2*)(A + r * PITCH + k0) = make_uint2(packh2(o[0], o[1]), packh2(o[2], o[3]));
            }
        }
        asm volatile("bar.sync 1, %0;" :: "n"(NCTHREADS) : "memory");   // consumers only

        // ldmatrix lane addresses (bytes)
        const uint32_t arow = (uint32_t)((wm * 16 + (lane & 15)) * PITCH + (lane >> 4) * 8) * 2;
        const uint32_t boff = (uint32_t)((wn * 16 + ((lane >> 4) & 1) * 8 + (lane & 7)) * PITCH
                               + ((lane >> 3) & 1) * 8) * 2;
        const uint32_t sA = sb + OFF_A;

        // epilogue coords (SMEM-local)
        const int er  = wm * 16 + (lane >> 2);      // rows er, er+8
        const int ejc = wn * 16 + ((lane & 3) << 1);
        const float* sR = (const float*)(smem + OFF_R);
        const int*   sC = (const int*)(smem + OFF_C);

        for (int t = 0; t < NT; t++) {
            const int s = t & 1;
            const uint32_t pc = ((uint32_t)t >> 1) & 1u;
            const int j0 = t * BN;

            mbar_wait(mb_fullB + s * 8, pc);

            // ---- MMA: acc = A*B (pure fp16) ----
            const uint32_t sB = sb + OFF_B + (uint32_t)s * B_MAT;
            float acc[2][4] = {};
            #pragma unroll 4
            for (int ks = 0; ks < 16; ks++) {
                const uint32_t k0b = (uint32_t)(ks * 16) * 2;
                uint32_t a[4], b[4];
                ldsm4(a, sA + arow + k0b);
                ldsm4(b, sB + boff + k0b);
                mma16816h(acc[0], a, b[0], b[1]);
                mma16816h(acc[1], a, b[2], b[3]);
            }

            mbar_wait(mb_fullRC + s * 8, pc);

            // ---- epilogue from staged SMEM ----
            const int sro = s * (RC_MAT / 4);
            #pragma unroll
            for (int ni = 0; ni < 2; ni++) {
                const int jc = ejc + ni * 8;
                if (j0 + jc < NTOP) {
                    #pragma unroll
                    for (int rr = 0; rr < 2; rr++) {
                        const int so = sro + (er + rr * 8) * RCP + jc;
                        float2 r2 = *(const float2*)(sR + so);
                        int2   c2 = *(const int2*)(sC + so);
                        if (c2.x == 1) { float m = sigmoidf(acc[ni][rr*2+0]); float z = (r2.x - m) * 10.f; lsum += LOGC - 0.5f * z * z; }
                        if (c2.y == 1) { float m = sigmoidf(acc[ni][rr*2+1]); float z = (r2.y - m) * 10.f; lsum += LOGC - 0.5f * z * z; }
                    }
                }
            }
            mbar_arrive(mb_empty + s * 8);   // stage free (B + R/C consumed)
        }
    }

    // ---- block reduction (producers contribute 0) ----
    #pragma unroll
    for (int o = 16; o > 0; o >>= 1)
        lsum += __shfl_xor_sync(0xFFFFFFFFu, lsum, o);
    if (lane == 0) red[warp] = lsum;
    __syncthreads();
    if (warp == 0) {
        float v = (lane < 20) ? red[lane] : 0.f;
        #pragma unroll
        for (int o = 16; o > 0; o >>= 1)
            v += __shfl_xor_sync(0xFFFFFFFFu, v, o);
        if (lane == 0) atomicAdd(out, v);
    }
}

// ---------------------------------------------------------------------------
extern "C" void kernel_launch(void* const* d_in, const int* in_sizes, int n_in,
                              void* d_out, int out_size)
{
    // Identify inputs by element count (dict order breaks ties:
    // V before noise at 256000, R before C at 40000000).
    const float *V = nullptr, *R = nullptr, *nw = nullptr, *U = nullptr;
    const float *W = nullptr, *Bb = nullptr, *noise = nullptr;
    const int* C = nullptr;
    int seen256k = 0, seen40m = 0;
    for (int i = 0; i < n_in; i++) {
        switch (in_sizes[i]) {
            case 256000:
                if (seen256k++ == 0) V = (const float*)d_in[i];
                else                 noise = (const float*)d_in[i];
                break;
            case 40000000:
                if (seen40m++ == 0) R = (const float*)d_in[i];
                else                C = (const int*)d_in[i];
                break;
            case 1000000:  nw = (const float*)d_in[i]; break;
            case 51200000: U  = (const float*)d_in[i]; break;
            case 5:        W  = (const float*)d_in[i]; break;
            case 1:        Bb = (const float*)d_in[i]; break;
            default: break; // Q unused
        }
    }
    float* out = (float*)d_out;

    cudaFuncSetAttribute(main_kernel, cudaFuncAttributeMaxDynamicSharedMemorySize, SMEM_BYTES);

    setup_kernel<<<32, 256>>>(V, nw, noise, out);
    main_kernel<<<TLTOT / BM, NTHREADS, SMEM_BYTES>>>(R, U, W, Bb, C, out);
}